// round 13
// baseline (speedup 1.0000x reference)
#include <cuda_runtime.h>
#include <cstdint>

#define BINS  30
#define EMB   100
#define NROW  491520
#define NWT   (NROW/16)        // 30720 16-row groups
#define NTHR  256
#define GRID  456              // 152 SMs x 3 CTAs
#define GP    (GRID*4)         // 1824 warp-pairs (4 pairs per CTA)

#define NPAD  112              // 14 n8 tiles (7 per warp half)
#define BST   40               // B row stride in fp16 (80 B)

// ---------------- helpers ----------------
__device__ __forceinline__ uint32_t smem_u32(const void* p) {
    uint32_t a;
    asm("{ .reg .u64 t; cvta.to.shared.u64 t, %1; cvt.u32.u64 %0, t; }" : "=r"(a) : "l"(p));
    return a;
}
__device__ __forceinline__ void sts128(uint32_t a, uint4 v) {
    asm volatile("st.shared.v4.b32 [%0], {%1,%2,%3,%4};" :: "r"(a), "r"(v.x), "r"(v.y), "r"(v.z), "r"(v.w) : "memory");
}
__device__ __forceinline__ void sts16(uint32_t a, unsigned short v) {
    asm volatile("st.shared.b16 [%0], %1;" :: "r"(a), "h"(v) : "memory");
}
__device__ __forceinline__ void ldm_x2(uint32_t& r0, uint32_t& r1, uint32_t a) {
    asm volatile("ldmatrix.sync.aligned.m8n8.x2.shared.b16 {%0,%1}, [%2];"
                 : "=r"(r0), "=r"(r1) : "r"(a));
}
// acc-in-place accumulate (D == C)
__device__ __forceinline__ void mma_f16(float& d0, float& d1, float& d2, float& d3,
                                        uint32_t a0, uint32_t a1, uint32_t a2, uint32_t a3,
                                        uint32_t b0, uint32_t b1) {
    asm volatile("mma.sync.aligned.m16n8k16.row.col.f32.f16.f16.f32 "
                 "{%0,%1,%2,%3}, {%4,%5,%6,%7}, {%8,%9}, {%0,%1,%2,%3};"
                 : "+f"(d0), "+f"(d1), "+f"(d2), "+f"(d3)
                 : "r"(a0), "r"(a1), "r"(a2), "r"(a3), "r"(b0), "r"(b1));
}
// separate C (used with constant-zero C regs: writes D without pre-init)
__device__ __forceinline__ void mma_f16_dc(float& d0, float& d1, float& d2, float& d3,
                                           uint32_t a0, uint32_t a1, uint32_t a2, uint32_t a3,
                                           uint32_t b0, uint32_t b1,
                                           float c0, float c1, float c2, float c3) {
    asm volatile("mma.sync.aligned.m16n8k16.row.col.f32.f16.f16.f32 "
                 "{%0,%1,%2,%3}, {%4,%5,%6,%7}, {%8,%9}, {%10,%11,%12,%13};"
                 : "=f"(d0), "=f"(d1), "=f"(d2), "=f"(d3)
                 : "r"(a0), "r"(a1), "r"(a2), "r"(a3), "r"(b0), "r"(b1),
                   "f"(c0), "f"(c1), "f"(c2), "f"(c3));
}
__device__ __forceinline__ uint32_t pack_f16x2(float lo, float hi) {
    uint32_t r;
    asm("cvt.rn.f16x2.f32 %0, %2, %1;" : "=r"(r) : "f"(lo), "f"(hi));
    return r;
}
__device__ __forceinline__ unsigned short f32_to_f16(float v) {
    unsigned short r;
    asm("cvt.rn.f16.f32 %0, %1;" : "=h"(r) : "f"(v));
    return r;
}
__device__ __forceinline__ float ex2f(float a) {
    float e; asm("ex2.approx.ftz.f32 %0, %1;" : "=f"(e) : "f"(a)); return e;
}
__device__ __forceinline__ float rcpf(float a) {
    float e; asm("rcp.approx.ftz.f32 %0, %1;" : "=f"(e) : "f"(a)); return e;
}

// ---------------------------------------------------------------------------
// Barrier-free persistent kernel, N split across warp pairs.
// Pair p handles 16-row groups p, p+GP, ...; half 0 -> n8 tiles 0-6,
// half 1 -> tiles 7-13 (stores masked to cols < 100). B in registers.
// ---------------------------------------------------------------------------
__global__ void __launch_bounds__(NTHR, 3)
main_kernel(const float* __restrict__ x,
            const float* __restrict__ W1,
            const float* __restrict__ Wl,
            const float* __restrict__ W2,
            float* __restrict__ out) {
    __shared__ float dsh[2][32];
    __shared__ __align__(16) unsigned short bsm[NPAD * BST];   // 8960 B

    const int tid  = threadIdx.x;
    const int wid  = tid >> 5;
    const int lane = tid & 31;
    const int c    = lane & 3;
    const int q    = lane >> 2;
    const int half = wid & 1;

    // ---- init: d-coefficients, warps 0 (x>0) and 1 (x<0); convergent collectives
    if (wid < 2) {
        const int s = wid, o = lane;
        float v = 0.f;
        if (o < BINS) {
            float w = W1[o];
            bool act = (s == 0) ? (w > 0.f) : (w < 0.f);
            v = act ? w : 0.01f * w;
        }
        float u = 0.f;
        #pragma unroll
        for (int i = 0; i < BINS; i++) {
            float vi = __shfl_sync(0xFFFFFFFFu, v, i);
            float wv = (o < BINS) ? Wl[o * BINS + i] : 0.f;
            u += wv * vi;
        }
        u += 0.1f * v;
        float ured = (o < BINS) ? u : ((s == 0) ? -3.0e38f : 3.0e38f);
        #pragma unroll
        for (int off = 16; off > 0; off >>= 1) {
            float t2 = __shfl_xor_sync(0xFFFFFFFFu, ured, off);
            ured = (s == 0) ? fmaxf(ured, t2) : fminf(ured, t2);
        }
        const float T_LOG2E = 0.5f * 1.44269504088896340736f;
        dsh[s][o] = (o < BINS) ? T_LOG2E * (u - ured) : 0.f;
    }

    // ---- init: B image (fp16) rows, cols 0..29 = w, 30..31 = 0; rows >=100 zero
    if (tid < NPAD) {
        const int n = tid;
        uint32_t brow = smem_u32(bsm) + (uint32_t)n * (BST * 2);
        if (n < EMB) {
            #pragma unroll
            for (int o = 0; o < BINS; o++)
                sts16(brow + (uint32_t)(2 * o), f32_to_f16(W2[n * BINS + o]));
            sts16(brow + 60, 0);
            sts16(brow + 62, 0);
        } else {
            uint4 z = make_uint4(0, 0, 0, 0);
            #pragma unroll
            for (int k = 0; k < 4; k++) sts128(brow + 16u * k, z);
        }
    }
    __syncthreads();   // the ONLY barrier in the kernel

    // ---- hoist this half's 7 B-fragment tiles into registers ----
    uint32_t Bf[7][2][2];
    {
        const uint32_t bb = smem_u32(bsm);
        const uint32_t radd = (uint32_t)((lane & 7) * (BST * 2) + ((lane >> 3) & 1) * 16);
        #pragma unroll
        for (int j = 0; j < 7; j++) {
            const int nj = half * 7 + j;
            #pragma unroll
            for (int kk = 0; kk < 2; kk++) {
                uint32_t a = bb + (uint32_t)(8 * nj * (BST * 2)) + radd + (uint32_t)kk * 32u;
                ldm_x2(Bf[j][kk][0], Bf[j][kk][1], a);
            }
        }
    }

    const float* d0p = dsh[0];
    const float* d1p = dsh[1];
    const int c2 = 2 * c;
    const float z0 = 0.f;   // constant-zero C operands

    // ---- independent per-pair tile loop (no barriers) ----
    int wt = blockIdx.x * 4 + (wid >> 1);
    float xa0 = 0.f, xa1 = 0.f;
    if (wt < NWT) {
        xa0 = x[(size_t)wt * 16 + q];
        xa1 = x[(size_t)wt * 16 + q + 8];
    }

    for (; wt < NWT; wt += GP) {
        // prefetch next group's x
        const int nwt = wt + GP;
        float xb0 = 0.f, xb1 = 0.f;
        if (nwt < NWT) {
            xb0 = x[(size_t)nwt * 16 + q];
            xb1 = x[(size_t)nwt * 16 + q + 8];
        }

        // softmax directly in A-fragment layout, rows q (R0) and q+8 (R1)
        uint32_t paR0[2][2], paR1[2][2];
        {
            const float* dp = (xa0 > 0.f) ? d0p : d1p;
            float e0 = ex2f(xa0 * dp[c2]);
            float e1 = ex2f(xa0 * dp[c2 + 1]);
            float e2 = ex2f(xa0 * dp[c2 + 8]);
            float e3 = ex2f(xa0 * dp[c2 + 9]);
            float e4 = ex2f(xa0 * dp[c2 + 16]);
            float e5 = ex2f(xa0 * dp[c2 + 17]);
            float e6 = (c2 + 24 < BINS) ? ex2f(xa0 * dp[c2 + 24]) : 0.f;
            float e7 = (c2 + 25 < BINS) ? ex2f(xa0 * dp[c2 + 25]) : 0.f;
            float Z0 = ((e0 + e1) + (e2 + e3)) + ((e4 + e5) + (e6 + e7));
            Z0 += __shfl_xor_sync(0xFFFFFFFFu, Z0, 1);
            Z0 += __shfl_xor_sync(0xFFFFFFFFu, Z0, 2);
            float iz0 = rcpf(Z0);
            paR0[0][0] = pack_f16x2(e0 * iz0, e1 * iz0);
            paR0[0][1] = pack_f16x2(e2 * iz0, e3 * iz0);
            paR0[1][0] = pack_f16x2(e4 * iz0, e5 * iz0);
            paR0[1][1] = pack_f16x2(e6 * iz0, e7 * iz0);

            const float* dq2 = (xa1 > 0.f) ? d0p : d1p;
            float f0 = ex2f(xa1 * dq2[c2]);
            float f1 = ex2f(xa1 * dq2[c2 + 1]);
            float f2 = ex2f(xa1 * dq2[c2 + 8]);
            float f3 = ex2f(xa1 * dq2[c2 + 9]);
            float f4 = ex2f(xa1 * dq2[c2 + 16]);
            float f5 = ex2f(xa1 * dq2[c2 + 17]);
            float f6 = (c2 + 24 < BINS) ? ex2f(xa1 * dq2[c2 + 24]) : 0.f;
            float f7 = (c2 + 25 < BINS) ? ex2f(xa1 * dq2[c2 + 25]) : 0.f;
            float Z1 = ((f0 + f1) + (f2 + f3)) + ((f4 + f5) + (f6 + f7));
            Z1 += __shfl_xor_sync(0xFFFFFFFFu, Z1, 1);
            Z1 += __shfl_xor_sync(0xFFFFFFFFu, Z1, 2);
            float iz1 = rcpf(Z1);
            paR1[0][0] = pack_f16x2(f0 * iz1, f1 * iz1);
            paR1[0][1] = pack_f16x2(f2 * iz1, f3 * iz1);
            paR1[1][0] = pack_f16x2(f4 * iz1, f5 * iz1);
            paR1[1][1] = pack_f16x2(f6 * iz1, f7 * iz1);
        }

        // MMA: 7 n8 tiles x 2 k16 steps; kk0 writes acc via zero-C (no init MOVs)
        float acc[7][4];
        #pragma unroll
        for (int j = 0; j < 7; j++) {
            mma_f16_dc(acc[j][0], acc[j][1], acc[j][2], acc[j][3],
                       paR0[0][0], paR1[0][0], paR0[0][1], paR1[0][1],
                       Bf[j][0][0], Bf[j][0][1], z0, z0, z0, z0);
        }
        #pragma unroll
        for (int j = 0; j < 7; j++) {
            mma_f16(acc[j][0], acc[j][1], acc[j][2], acc[j][3],
                    paR0[1][0], paR1[1][0], paR0[1][1], paR1[1][1],
                    Bf[j][1][0], Bf[j][1][1]);
        }

        // direct fragment stores (quads write packed 32B sectors)
        {
            float* row0 = out + (size_t)(wt * 16 + q) * EMB;
            float* row1 = row0 + (size_t)8 * EMB;
            if (half == 0) {
                #pragma unroll
                for (int j = 0; j < 7; j++) {
                    const int col = 8 * j + c2;            // cols 0..55
                    float2 v0; v0.x = acc[j][0]; v0.y = acc[j][1];
                    float2 v1; v1.x = acc[j][2]; v1.y = acc[j][3];
                    *reinterpret_cast<float2*>(row0 + col) = v0;
                    *reinterpret_cast<float2*>(row1 + col) = v1;
                }
            } else {
                #pragma unroll
                for (int j = 0; j < 5; j++) {
                    const int col = 56 + 8 * j + c2;       // cols 56..95
                    float2 v0; v0.x = acc[j][0]; v0.y = acc[j][1];
                    float2 v1; v1.x = acc[j][2]; v1.y = acc[j][3];
                    *reinterpret_cast<float2*>(row0 + col) = v0;
                    *reinterpret_cast<float2*>(row1 + col) = v1;
                }
                if (c2 < 4) {                              // cols 96..99
                    const int col = 96 + c2;
                    float2 v0; v0.x = acc[5][0]; v0.y = acc[5][1];
                    float2 v1; v1.x = acc[5][2]; v1.y = acc[5][3];
                    *reinterpret_cast<float2*>(row0 + col) = v0;
                    *reinterpret_cast<float2*>(row1 + col) = v1;
                }
                // j == 6 (cols 104..111): padding, not stored
            }
        }

        xa0 = xb0;
        xa1 = xb1;
    }
}

// ---------------------------------------------------------------------------
extern "C" void kernel_launch(void* const* d_in, const int* in_sizes, int n_in,
                              void* d_out, int out_size) {
    const float* x  = (const float*)d_in[0];   // (16384, 1, 30)
    const float* W1 = (const float*)d_in[1];   // (30, 1)
    const float* Wl = (const float*)d_in[2];   // (30, 30)
    const float* W2 = (const float*)d_in[3];   // (100, 30)
    float* out = (float*)d_out;                // (16384, 3000)

    main_kernel<<<GRID, NTHR>>>(x, W1, Wl, W2, out);
}

// round 17
// speedup vs baseline: 1.8654x; 1.8654x over previous
#include <cuda_runtime.h>
#include <cstdint>

#define BINS  30
#define EMB   100
#define NROW  491520
#define NWT   (NROW/16)        // 30720 warp-tiles (16 rows each)
#define NTHR  256
#define GRID  304              // 152 SMs x 2 CTAs
#define GW    (GRID*(NTHR/32)) // 2432 warps total

#define NPAD  104
#define BST   40               // B row stride in fp16 (80 B)
#define TILE_BYTES 6400        // 16 rows x 100 f32, contiguous in gmem
#define DYN_SMEM (8 * 2 * TILE_BYTES)   // 102400 B stage (8 warps, dbl-buffered)

// ---------------- helpers ----------------
__device__ __forceinline__ uint32_t smem_u32(const void* p) {
    uint32_t a;
    asm("{ .reg .u64 t; cvta.to.shared.u64 t, %1; cvt.u32.u64 %0, t; }" : "=r"(a) : "l"(p));
    return a;
}
__device__ __forceinline__ void sts128(uint32_t a, uint4 v) {
    asm volatile("st.shared.v4.b32 [%0], {%1,%2,%3,%4};" :: "r"(a), "r"(v.x), "r"(v.y), "r"(v.z), "r"(v.w) : "memory");
}
__device__ __forceinline__ void sts64f(uint32_t a, float x, float y) {
    asm volatile("st.shared.v2.f32 [%0], {%1,%2};" :: "r"(a), "f"(x), "f"(y) : "memory");
}
__device__ __forceinline__ void sts16(uint32_t a, unsigned short v) {
    asm volatile("st.shared.b16 [%0], %1;" :: "r"(a), "h"(v) : "memory");
}
__device__ __forceinline__ void ldm_x2(uint32_t& r0, uint32_t& r1, uint32_t a) {
    asm volatile("ldmatrix.sync.aligned.m8n8.x2.shared.b16 {%0,%1}, [%2];"
                 : "=r"(r0), "=r"(r1) : "r"(a));
}
__device__ __forceinline__ void mma_f16(float& d0, float& d1, float& d2, float& d3,
                                        uint32_t a0, uint32_t a1, uint32_t a2, uint32_t a3,
                                        uint32_t b0, uint32_t b1) {
    asm volatile("mma.sync.aligned.m16n8k16.row.col.f32.f16.f16.f32 "
                 "{%0,%1,%2,%3}, {%4,%5,%6,%7}, {%8,%9}, {%0,%1,%2,%3};"
                 : "+f"(d0), "+f"(d1), "+f"(d2), "+f"(d3)
                 : "r"(a0), "r"(a1), "r"(a2), "r"(a3), "r"(b0), "r"(b1));
}
// separate C (zero regs) -> writes D without acc pre-init
__device__ __forceinline__ void mma_f16_dc(float& d0, float& d1, float& d2, float& d3,
                                           uint32_t a0, uint32_t a1, uint32_t a2, uint32_t a3,
                                           uint32_t b0, uint32_t b1,
                                           float c0, float c1, float c2, float c3) {
    asm volatile("mma.sync.aligned.m16n8k16.row.col.f32.f16.f16.f32 "
                 "{%0,%1,%2,%3}, {%4,%5,%6,%7}, {%8,%9}, {%10,%11,%12,%13};"
                 : "=f"(d0), "=f"(d1), "=f"(d2), "=f"(d3)
                 : "r"(a0), "r"(a1), "r"(a2), "r"(a3), "r"(b0), "r"(b1),
                   "f"(c0), "f"(c1), "f"(c2), "f"(c3));
}
__device__ __forceinline__ uint32_t pack_f16x2(float lo, float hi) {
    uint32_t r;
    asm("cvt.rn.f16x2.f32 %0, %2, %1;" : "=r"(r) : "f"(lo), "f"(hi));
    return r;
}
__device__ __forceinline__ unsigned short f32_to_f16(float v) {
    unsigned short r;
    asm("cvt.rn.f16.f32 %0, %1;" : "=h"(r) : "f"(v));
    return r;
}
__device__ __forceinline__ float ex2f(float a) {
    float e; asm("ex2.approx.ftz.f32 %0, %1;" : "=f"(e) : "f"(a)); return e;
}
__device__ __forceinline__ float rcpf(float a) {
    float e; asm("rcp.approx.ftz.f32 %0, %1;" : "=f"(e) : "f"(a)); return e;
}
__device__ __forceinline__ void bulk_s2g(void* gptr, uint32_t saddr, uint32_t bytes) {
    asm volatile("cp.async.bulk.global.shared::cta.bulk_group [%0], [%1], %2;"
                 :: "l"(gptr), "r"(saddr), "r"(bytes) : "memory");
}

// ---------------------------------------------------------------------------
// Barrier-free persistent kernel with TMA bulk stores.
// Per warp: softmax in A-fragment layout -> 26 HMMA (B in regs) -> stage
// 6400B in smem -> cp.async.bulk S2G (contiguous). Double-buffered stage.
// ---------------------------------------------------------------------------
__global__ void __launch_bounds__(NTHR, 2)
main_kernel(const float* __restrict__ x,
            const float* __restrict__ W1,
            const float* __restrict__ Wl,
            const float* __restrict__ W2,
            float* __restrict__ out) {
    extern __shared__ char raw[];                 // stage: 8 warps x 2 x 6400 B
    __shared__ float dsh[2][32];
    __shared__ __align__(16) unsigned short bsm[NPAD * BST];

    const int tid  = threadIdx.x;
    const int wid  = tid >> 5;
    const int lane = tid & 31;
    const int c    = lane & 3;
    const int q    = lane >> 2;

    // ---- init: d-coefficients, warps 0 (x>0) and 1 (x<0); convergent collectives
    if (wid < 2) {
        const int s = wid, o = lane;
        float v = 0.f;
        if (o < BINS) {
            float w = W1[o];
            bool act = (s == 0) ? (w > 0.f) : (w < 0.f);
            v = act ? w : 0.01f * w;
        }
        float u = 0.f;
        #pragma unroll
        for (int i = 0; i < BINS; i++) {
            float vi = __shfl_sync(0xFFFFFFFFu, v, i);
            float wv = (o < BINS) ? Wl[o * BINS + i] : 0.f;
            u += wv * vi;
        }
        u += 0.1f * v;
        float ured = (o < BINS) ? u : ((s == 0) ? -3.0e38f : 3.0e38f);
        #pragma unroll
        for (int off = 16; off > 0; off >>= 1) {
            float t2 = __shfl_xor_sync(0xFFFFFFFFu, ured, off);
            ured = (s == 0) ? fmaxf(ured, t2) : fminf(ured, t2);
        }
        const float T_LOG2E = 0.5f * 1.44269504088896340736f;
        dsh[s][o] = (o < BINS) ? T_LOG2E * (u - ured) : 0.f;
    }

    // ---- init: B image (fp16) rows, cols 0..29 = w, 30..31 = 0; rows >=100 zero
    if (tid < NPAD) {
        const int n = tid;
        uint32_t brow = smem_u32(bsm) + (uint32_t)n * (BST * 2);
        if (n < EMB) {
            #pragma unroll
            for (int o = 0; o < BINS; o++)
                sts16(brow + (uint32_t)(2 * o), f32_to_f16(W2[n * BINS + o]));
            sts16(brow + 60, 0);
            sts16(brow + 62, 0);
        } else {
            uint4 z = make_uint4(0, 0, 0, 0);
            #pragma unroll
            for (int k = 0; k < 4; k++) sts128(brow + 16u * k, z);
        }
    }
    __syncthreads();   // the ONLY CTA barrier

    // ---- hoist B fragments into registers ----
    uint32_t Bf[13][2][2];
    {
        const uint32_t bb = smem_u32(bsm);
        const uint32_t radd = (uint32_t)((lane & 7) * (BST * 2) + ((lane >> 3) & 1) * 16);
        #pragma unroll
        for (int nj = 0; nj < 13; nj++) {
            #pragma unroll
            for (int kk = 0; kk < 2; kk++) {
                uint32_t a = bb + (uint32_t)(8 * nj * (BST * 2)) + radd + (uint32_t)kk * 32u;
                ldm_x2(Bf[nj][kk][0], Bf[nj][kk][1], a);
            }
        }
    }

    const float* d0p = dsh[0];
    const float* d1p = dsh[1];
    const int c2 = 2 * c;
    const float z0 = 0.f;
    const uint32_t stage0 = smem_u32(raw) + (uint32_t)wid * (2 * TILE_BYTES);

    // ---- independent per-warp tile loop (no CTA barriers) ----
    int wt = blockIdx.x * (NTHR / 32) + wid;
    float xa0 = 0.f, xa1 = 0.f;
    if (wt < NWT) {
        xa0 = x[(size_t)wt * 16 + q];
        xa1 = x[(size_t)wt * 16 + q + 8];
    }
    int buf = 0;

    for (; wt < NWT; wt += GW, buf ^= 1) {
        // prefetch next warp-tile's x
        const int nwt = wt + GW;
        float xb0 = 0.f, xb1 = 0.f;
        if (nwt < NWT) {
            xb0 = x[(size_t)nwt * 16 + q];
            xb1 = x[(size_t)nwt * 16 + q + 8];
        }

        // softmax directly in A-fragment layout, rows q (R0) and q+8 (R1)
        uint32_t paR0[2][2], paR1[2][2];
        {
            const float* dp = (xa0 > 0.f) ? d0p : d1p;
            float e0 = ex2f(xa0 * dp[c2]);
            float e1 = ex2f(xa0 * dp[c2 + 1]);
            float e2 = ex2f(xa0 * dp[c2 + 8]);
            float e3 = ex2f(xa0 * dp[c2 + 9]);
            float e4 = ex2f(xa0 * dp[c2 + 16]);
            float e5 = ex2f(xa0 * dp[c2 + 17]);
            float e6 = (c2 + 24 < BINS) ? ex2f(xa0 * dp[c2 + 24]) : 0.f;
            float e7 = (c2 + 25 < BINS) ? ex2f(xa0 * dp[c2 + 25]) : 0.f;
            float Z0 = ((e0 + e1) + (e2 + e3)) + ((e4 + e5) + (e6 + e7));
            Z0 += __shfl_xor_sync(0xFFFFFFFFu, Z0, 1);
            Z0 += __shfl_xor_sync(0xFFFFFFFFu, Z0, 2);
            float iz0 = rcpf(Z0);
            paR0[0][0] = pack_f16x2(e0 * iz0, e1 * iz0);
            paR0[0][1] = pack_f16x2(e2 * iz0, e3 * iz0);
            paR0[1][0] = pack_f16x2(e4 * iz0, e5 * iz0);
            paR0[1][1] = pack_f16x2(e6 * iz0, e7 * iz0);

            const float* dq2 = (xa1 > 0.f) ? d0p : d1p;
            float f0 = ex2f(xa1 * dq2[c2]);
            float f1 = ex2f(xa1 * dq2[c2 + 1]);
            float f2 = ex2f(xa1 * dq2[c2 + 8]);
            float f3 = ex2f(xa1 * dq2[c2 + 9]);
            float f4 = ex2f(xa1 * dq2[c2 + 16]);
            float f5 = ex2f(xa1 * dq2[c2 + 17]);
            float f6 = (c2 + 24 < BINS) ? ex2f(xa1 * dq2[c2 + 24]) : 0.f;
            float f7 = (c2 + 25 < BINS) ? ex2f(xa1 * dq2[c2 + 25]) : 0.f;
            float Z1 = ((f0 + f1) + (f2 + f3)) + ((f4 + f5) + (f6 + f7));
            Z1 += __shfl_xor_sync(0xFFFFFFFFu, Z1, 1);
            Z1 += __shfl_xor_sync(0xFFFFFFFFu, Z1, 2);
            float iz1 = rcpf(Z1);
            paR1[0][0] = pack_f16x2(f0 * iz1, f1 * iz1);
            paR1[0][1] = pack_f16x2(f2 * iz1, f3 * iz1);
            paR1[1][0] = pack_f16x2(f4 * iz1, f5 * iz1);
            paR1[1][1] = pack_f16x2(f6 * iz1, f7 * iz1);
        }

        // MMA: kk0 via zero-C (no acc init), kk1 accumulates
        float acc[13][4];
        #pragma unroll
        for (int nj = 0; nj < 13; nj++) {
            mma_f16_dc(acc[nj][0], acc[nj][1], acc[nj][2], acc[nj][3],
                       paR0[0][0], paR1[0][0], paR0[0][1], paR1[0][1],
                       Bf[nj][0][0], Bf[nj][0][1], z0, z0, z0, z0);
        }
        #pragma unroll
        for (int nj = 0; nj < 13; nj++) {
            mma_f16(acc[nj][0], acc[nj][1], acc[nj][2], acc[nj][3],
                    paR0[1][0], paR1[1][0], paR0[1][1], paR1[1][1],
                    Bf[nj][1][0], Bf[nj][1][1]);
        }

        // ---- stage to smem, then TMA bulk copy (contiguous 6400 B) ----
        // ensure this buffer's previous copy has consumed its smem
        if (lane == 0) asm volatile("cp.async.bulk.wait_group.read 1;" ::: "memory");
        __syncwarp();

        const uint32_t sb = stage0 + (uint32_t)buf * TILE_BYTES;
        {
            const uint32_t r0off = sb + (uint32_t)(q * EMB + c2) * 4u;
            const uint32_t r1off = r0off + (uint32_t)(8 * EMB) * 4u;
            #pragma unroll
            for (int nj = 0; nj < 12; nj++) {
                sts64f(r0off + (uint32_t)(8 * nj) * 4u, acc[nj][0], acc[nj][1]);
                sts64f(r1off + (uint32_t)(8 * nj) * 4u, acc[nj][2], acc[nj][3]);
            }
            if (c2 < 4) {   // cols 96..99
                sts64f(r0off + 96u * 4u, acc[12][0], acc[12][1]);
                sts64f(r1off + 96u * 4u, acc[12][2], acc[12][3]);
            }
        }
        __syncwarp();
        if (lane == 0) {
            asm volatile("fence.proxy.async.shared::cta;" ::: "memory");
            bulk_s2g(out + (size_t)wt * 16 * EMB, sb, TILE_BYTES);
            asm volatile("cp.async.bulk.commit_group;" ::: "memory");
        }

        xa0 = xb0;
        xa1 = xb1;
    }

    // drain outstanding bulk copies before exit
    if (lane == 0) asm volatile("cp.async.bulk.wait_group 0;" ::: "memory");
}

// ---------------------------------------------------------------------------
extern "C" void kernel_launch(void* const* d_in, const int* in_sizes, int n_in,
                              void* d_out, int out_size) {
    const float* x  = (const float*)d_in[0];   // (16384, 1, 30)
    const float* W1 = (const float*)d_in[1];   // (30, 1)
    const float* Wl = (const float*)d_in[2];   // (30, 30)
    const float* W2 = (const float*)d_in[3];   // (100, 30)
    float* out = (float*)d_out;                // (16384, 3000)

    cudaFuncSetAttribute(main_kernel, cudaFuncAttributeMaxDynamicSharedMemorySize, DYN_SMEM);
    main_kernel<<<GRID, NTHR, DYN_SMEM>>>(x, W1, Wl, W2, out);
}